// round 17
// baseline (speedup 1.0000x reference)
#include <cuda_runtime.h>
#include <cstdint>

#define L      2048
#define C_IN   16
#define GROUPS 4
#define SLOT   32          // fixed padded slots per (ch,row); overflow -> g_list
#define SENT   0x7FFFFFFF
#define CAP    512         // smem survivor capacity per row; spill -> g_list
#define ACCW   2056        // padded acc row: idx = out_col + 4, range [3,2052]

// Padded fast-path lists: SLOT entries per (ch,row), column-sorted, padded
// with sentinel col = INT_MAX. Always fully written for every row.
__device__ float2 g_slot[(size_t)C_IN * L * SLOT];
// Full-stride scratch: survivor spill + overflow lists (correctness fallback).
__device__ float2 g_list[(size_t)C_IN * L * L];
__device__ int    g_cnt[C_IN * L];

// ---------------------------------------------------------------------------
// Kernel 1: PAIRED row-wise sparsemax. Block (bx, ch) handles rows
// rA = bx and rB = 2047-bx as one concatenated vector:
//   concat = [row B cols 0..lenB) ++ pad(<=3, -inf) ++ [row A cols 0..lenA)
// lenB padded to mult of 4 => both segments float4-aligned. Total 2049..2052;
// 256 threads x 8 cover [0,2048), thread 0 takes the <=4 tail elements.
// One barrier set serves both rows; warps 0/1 run the two Michelot tails
// concurrently. Survivors beyond CAP spill to g_list (always correct).
// ---------------------------------------------------------------------------
__global__ __launch_bounds__(256) void sparsemax_kernel(const float* __restrict__ scores)
{
    const int bx   = blockIdx.x;          // 0..1023
    const int ch   = blockIdx.y;
    const int tid  = threadIdx.x;
    const int lane = tid & 31;
    const int warp = tid >> 5;            // 8 warps
    const int rA = bx, rB = 2047 - bx;
    const int lenA = rA + 1, lenB = rB + 1;        // lenB >= 1025 > lenA
    const int lenBp = (lenB + 3) & ~3;             // <= 2048
    const int tot_c = lenBp + lenA;                // 2049..2052
    const size_t baseA = ((size_t)ch * L + rA) * (size_t)L;
    const size_t baseB = ((size_t)ch * L + rB) * (size_t)L;
    const int c0 = tid * 8;

    // ---- loads: bulk threads use 2 aligned float4; boundaries scalar ----
    float z[8];
    if (c0 + 8 <= lenB) {                          // pure row-B region
        const float4 a = *reinterpret_cast<const float4*>(scores + baseB + c0);
        const float4 b = *reinterpret_cast<const float4*>(scores + baseB + c0 + 4);
        z[0]=a.x; z[1]=a.y; z[2]=a.z; z[3]=a.w;
        z[4]=b.x; z[5]=b.y; z[6]=b.z; z[7]=b.w;
    } else if (c0 >= lenBp && c0 - lenBp + 8 <= lenA) {   // pure row-A region
        const int col0 = c0 - lenBp;               // mult of 4 => aligned
        const float4 a = *reinterpret_cast<const float4*>(scores + baseA + col0);
        const float4 b = *reinterpret_cast<const float4*>(scores + baseA + col0 + 4);
        z[0]=a.x; z[1]=a.y; z[2]=a.z; z[3]=a.w;
        z[4]=b.x; z[5]=b.y; z[6]=b.z; z[7]=b.w;
    } else {                                       // straddle / pad / tail
#pragma unroll
        for (int x = 0; x < 8; x++) {
            const int c = c0 + x;
            float v = -INFINITY;
            if (c < lenB)                          v = scores[baseB + c];
            else if (c >= lenBp && c - lenBp < lenA) v = scores[baseA + c - lenBp];
            z[x] = v;
        }
    }
    // tail elements: concat positions 2048..tot_c-1 (always row A), thread 0
    float zx[4] = {-INFINITY, -INFINITY, -INFINITY, -INFINITY};
    const int nx = tot_c - 2048;                   // 1..4
    if (tid == 0) {
#pragma unroll
        for (int k = 0; k < 4; k++)
            if (k < nx) zx[k] = scores[baseA + (2048 + k - lenBp)];
    }

    __shared__ float  smaxA[8], smaxB[8];
    __shared__ int    swtot[8];
    __shared__ int    s_ex;
    __shared__ float2 slA[CAP], slB[CAP];

    // ---- dual row max (one barrier) ----
    float mB = -INFINITY, mA = -INFINITY;
#pragma unroll
    for (int x = 0; x < 8; x++) {
        const int c = c0 + x;
        if (c < lenB) mB = fmaxf(mB, z[x]); else mA = fmaxf(mA, z[x]);
    }
    if (tid == 0) {
#pragma unroll
        for (int k = 0; k < 4; k++) mA = fmaxf(mA, zx[k]);
    }
#pragma unroll
    for (int o = 16; o > 0; o >>= 1) {
        mB = fmaxf(mB, __shfl_xor_sync(0xffffffffu, mB, o));
        mA = fmaxf(mA, __shfl_xor_sync(0xffffffffu, mA, o));
    }
    if (lane == 0) { smaxB[warp] = mB; smaxA[warp] = mA; }
    __syncthreads();                                           // (1)
    float t0B = smaxB[0], t0A = smaxA[0];
#pragma unroll
    for (int w = 1; w < 8; w++) {
        t0B = fmaxf(t0B, smaxB[w]);
        t0A = fmaxf(t0A, smaxA[w]);
    }
    t0B -= 1.0f; t0A -= 1.0f;          // tau* in [max-1, max) for each row

    // ---- dual survivor mask + packed (B | A<<16) scan ----
    unsigned msk = 0; int cB = 0, cA = 0;
#pragma unroll
    for (int x = 0; x < 8; x++) {
        const int c = c0 + x;
        const bool inB = (c < lenB);
        if (z[x] > (inB ? t0B : t0A)) { msk |= 1u << x; if (inB) cB++; else cA++; }
    }
    const int packed = cB | (cA << 16);
    int v = packed;
#pragma unroll
    for (int o = 1; o < 32; o <<= 1) {
        const int n = __shfl_up_sync(0xffffffffu, v, o);
        if (lane >= o) v += n;
    }
    if (lane == 31) swtot[warp] = v;
    __syncthreads();                                           // (2)
    int wb = 0, totp = 0;
#pragma unroll
    for (int w = 0; w < 8; w++) { if (w < warp) wb += swtot[w]; totp += swtot[w]; }
    const int excl = v - packed + wb;          // packed exclusive prefix
    int pB = excl & 0xFFFF;
    int pA = excl >> 16;
    const int totB = totp & 0xFFFF;
    const int totAmain = totp >> 16;

    // ---- sorted compaction (smem with g_list spill) ----
#pragma unroll
    for (int x = 0; x < 8; x++) {
        if ((msk >> x) & 1u) {
            const int c = c0 + x;
            if (c < lenB) {
                const float2 e = make_float2(__int_as_float(c), z[x]);
                if (pB < CAP) slB[pB] = e; else g_list[baseB + pB] = e;
                pB++;
            } else {
                const float2 e = make_float2(__int_as_float(c - lenBp), z[x]);
                if (pA < CAP) slA[pA] = e; else g_list[baseA + pA] = e;
                pA++;
            }
        }
    }
    if (tid == 0) {                              // tail elems append to A end
        int kp = totAmain, ex = 0;
#pragma unroll
        for (int k = 0; k < 4; k++) {
            if (k < nx && zx[k] > t0A) {
                const float2 e = make_float2(__int_as_float(2048 + k - lenBp), zx[k]);
                if (kp < CAP) slA[kp] = e; else g_list[baseA + kp] = e;
                kp++; ex++;
            }
        }
        s_ex = ex;
    }
    __syncthreads();                                           // (3)
    if (warp >= 2) return;                       // warps 2-7 done

    // ---- warp 0 -> row B, warp 1 -> row A: Michelot + final write ----
    const bool isA  = (warp == 1);
    const int row   = isA ? rA : rB;
    const size_t gb = isA ? baseA : baseB;
    const float2* sl = isA ? slA : slB;
    const int total = isA ? (totAmain + s_ex) : totB;
    float tau       = isA ? t0A : t0B;

    int prev = -1;
    for (int it = 0; it < 32; it++) {
        float S = 0.0f, C = 0.0f;
        for (int n = lane; n < total; n += 32) {
            const float y = (n < CAP) ? sl[n].y : g_list[gb + n].y;
            if (y > tau) { S += y; C += 1.0f; }
        }
#pragma unroll
        for (int o = 16; o > 0; o >>= 1) {
            S += __shfl_xor_sync(0xffffffffu, S, o);
            C += __shfl_xor_sync(0xffffffffu, C, o);
        }
        const int ci = (int)C;                   // >=1 always (argmax survives)
        tau = (S - 1.0f) / C;
        if (ci == prev) break;                   // support stable -> converged
        prev = ci;
    }

    float2* slot = g_slot + (size_t)(ch * L + row) * SLOT;
    int opos = 0;
    for (int n0 = 0; n0 < total; n0 += 32) {
        const int n = n0 + lane;
        float2 e; bool keep = false;
        if (n < total) {
            e = (n < CAP) ? sl[n] : g_list[gb + n];
            keep = (e.y > tau);
        }
        const unsigned b = __ballot_sync(0xffffffffu, keep);
        if (keep) {
            const int k = opos + __popc(b & ((1u << lane) - 1u));
            const float2 w = make_float2(e.x, e.y - tau);
            if (k < SLOT) slot[k] = w;
            g_list[gb + k] = w;                  // overflow-safe full copy
        }
        opos += __popc(b);
    }
    for (int n = opos + lane; n < SLOT; n += 32)
        slot[n] = make_float2(__int_as_float(SENT), 0.0f);
    if (lane == 0) g_cnt[ch * L + row] = opos;
}

// ---------------------------------------------------------------------------
// Kernel 2: grouped 3x3 conv, SCATTER formulation, FULL-ROW stores.
// (unchanged from the measured 57.2us round-16 version)
// ---------------------------------------------------------------------------
__global__ __launch_bounds__(256) void conv_sparse_kernel(const float* __restrict__ weight,
                                                          const float* __restrict__ bias,
                                                          float* __restrict__ out)
{
    __shared__ float wsm[144];          // [4 oc][4 ic][3][3]
    __shared__ float bsm[4];
    __shared__ float accs[4][ACCW];     // idx = out_col + 4; 32.9 KB

    const int i    = blockIdx.x;        // output row
    const int g    = blockIdx.y;        // group
    const int tid  = threadIdx.x;
    const int warp = tid >> 5;
    const int lane = tid & 31;

    if (tid < 144) wsm[tid] = weight[g * 144 + tid];
    if (tid >= 144 && tid < 148) bsm[tid - 144] = bias[g * 4 + (tid - 144)];

    // ---- issue list loads early: warp w owns list w (and 8+w for w<4) ----
    int   c0 = SENT, c1 = SENT;
    float v0 = 0.0f, v1 = 0.0f;
    {
        const int p   = warp;               // lists 0..7
        const int icc = p / 3, dr = p - icc * 3;
        const int r   = i + dr - 1;
        if (r >= 0 && r < L) {
            const float2 e = __ldg(&g_slot[(size_t)((g * 4 + icc) * L + r) * SLOT + lane]);
            c0 = __float_as_int(e.x); v0 = e.y;
        }
    }
    if (warp < 4) {
        const int p   = warp + 8;           // lists 8..11
        const int icc = p / 3, dr = p - icc * 3;
        const int r   = i + dr - 1;
        if (r >= 0 && r < L) {
            const float2 e = __ldg(&g_slot[(size_t)((g * 4 + icc) * L + r) * SLOT + lane]);
            c1 = __float_as_int(e.x); v1 = e.y;
        }
    }

    // ---- zero-init accs over the needed range idx in [0, i+8) ----
    const int n4 = min(ACCW >> 2, ((i + 8) >> 2) + 1);   // float4s per oc row
#pragma unroll
    for (int o = 0; o < 4; o++) {
        float4* a4 = reinterpret_cast<float4*>(&accs[o][0]);
        for (int k = tid; k < n4; k += 256)
            a4[k] = make_float4(0.f, 0.f, 0.f, 0.f);
    }
    __syncthreads();

    // ---- scatter phase ----
    {
        const int p = warp;
        const int icc = p / 3, dr = p - icc * 3;
        if (c0 != SENT) {
#pragma unroll
            for (int o = 0; o < 4; o++) {
                const int wb = ((o * 4 + icc) * 3 + dr) * 3;
#pragma unroll
                for (int dc = 0; dc < 3; dc++)
                    atomicAdd(&accs[o][c0 + 5 - dc], wsm[wb + dc] * v0);
            }
        }
        if (__shfl_sync(0xffffffffu, c0, 31) != SENT) {
            const int r  = i + dr - 1;
            const int gc = g * 4 + icc;
            const int cnt = g_cnt[gc * L + r];
            const float2* lst = g_list + ((size_t)gc * L + r) * (size_t)L;
            for (int n = SLOT + lane; n < cnt; n += 32) {
                const float2 e = __ldg(&lst[n]);
                const int c = __float_as_int(e.x);
#pragma unroll
                for (int o = 0; o < 4; o++) {
                    const int wb = ((o * 4 + icc) * 3 + dr) * 3;
#pragma unroll
                    for (int dc = 0; dc < 3; dc++)
                        atomicAdd(&accs[o][c + 5 - dc], wsm[wb + dc] * e.y);
                }
            }
        }
    }
    if (warp < 4) {
        const int p = warp + 8;
        const int icc = p / 3, dr = p - icc * 3;
        if (c1 != SENT) {
#pragma unroll
            for (int o = 0; o < 4; o++) {
                const int wb = ((o * 4 + icc) * 3 + dr) * 3;
#pragma unroll
                for (int dc = 0; dc < 3; dc++)
                    atomicAdd(&accs[o][c1 + 5 - dc], wsm[wb + dc] * v1);
            }
        }
        if (__shfl_sync(0xffffffffu, c1, 31) != SENT) {
            const int r  = i + dr - 1;
            const int gc = g * 4 + icc;
            const int cnt = g_cnt[gc * L + r];
            const float2* lst = g_list + ((size_t)gc * L + r) * (size_t)L;
            for (int n = SLOT + lane; n < cnt; n += 32) {
                const float2 e = __ldg(&lst[n]);
                const int c = __float_as_int(e.x);
#pragma unroll
                for (int o = 0; o < 4; o++) {
                    const int wb = ((o * 4 + icc) * 3 + dr) * 3;
#pragma unroll
                    for (int dc = 0; dc < 3; dc++)
                        atomicAdd(&accs[o][c + 5 - dc], wsm[wb + dc] * e.y);
                }
            }
        }
    }
    __syncthreads();

    // ---- dense phase: full-row store (acc+bias for j<=i, zeros beyond) ----
    const int oc = tid >> 6;
    const int cb = (tid & 63) * 4;
    const float b = bsm[oc];
    float* orow = out + ((size_t)(g * 4 + oc) * L + i) * (size_t)L;
    for (int j = cb; j < L; j += 256) {
        float4 vq = make_float4(0.f, 0.f, 0.f, 0.f);
        if (j + 3 <= i) {
            const float4 a = *reinterpret_cast<const float4*>(&accs[oc][j + 4]);
            vq.x = a.x + b; vq.y = a.y + b; vq.z = a.z + b; vq.w = a.w + b;
        } else if (j <= i) {
            const float4 a = *reinterpret_cast<const float4*>(&accs[oc][j + 4]);
            const float va[4] = {a.x, a.y, a.z, a.w};
            float vo[4];
#pragma unroll
            for (int x = 0; x < 4; x++)
                vo[x] = (j + x <= i) ? (va[x] + b) : 0.0f;
            vq.x = vo[0]; vq.y = vo[1]; vq.z = vo[2]; vq.w = vo[3];
        }
        *reinterpret_cast<float4*>(orow + j) = vq;
    }
}

// ---------------------------------------------------------------------------
extern "C" void kernel_launch(void* const* d_in, const int* in_sizes, int n_in,
                              void* d_out, int out_size)
{
    const float* scores = (const float*)d_in[0];
    const float* weight = (const float*)d_in[1];
    const float* bias   = (const float*)d_in[2];
    float* out = (float*)d_out;

    sparsemax_kernel<<<dim3(L / 2, C_IN), 256>>>(scores);
    conv_sparse_kernel<<<dim3(L, GROUPS), 256>>>(weight, bias, out);
}